// round 14
// baseline (speedup 1.0000x reference)
#include <cuda_runtime.h>
#include <cuda_fp16.h>
#include <cstdint>
#include <cmath>

#define TQ   4096
#define DM   1024
#define NH   16
#define DH   64
#define KW   (DM / 2)          // k-dim in fp16x2 words = 512

// Scratch (__device__ globals: allocation-free rule)
__device__ __half    g_qkv[(size_t)TQ * 3 * DM];     // [t][3c] fp16, Q pre-scaled (incl log2e)
__device__ uint32_t  g_att[(size_t)TQ * KW];         // attn out fp16 words (canonical)
__device__ uint32_t  g_xw[(size_t)TQ * KW];          // x fp16 words
__device__ uint32_t  g_wqkvT[(size_t)3 * DM * KW];   // w_qkv^T fp16 words [3DM][KW]
__device__ uint32_t  g_wprojT[(size_t)DM * KW];      // w_proj^T fp16 words [DM][KW]

// ---------------------------------------------------------------------------
// helpers
// ---------------------------------------------------------------------------
__device__ __forceinline__ uint32_t packh2(float a, float b) {
    __half2 h = __floats2half2_rn(a, b);
    return *reinterpret_cast<uint32_t*>(&h);
}
__device__ __forceinline__ uint32_t h2exp2u(uint32_t x) {   // 2^x on both halves
    uint32_t r;
    asm("ex2.approx.f16x2 %0, %1;" : "=r"(r) : "r"(x));
    return r;
}

__device__ __forceinline__ void mma_f16(float* d, const uint32_t* a,
                                        uint32_t b0, uint32_t b1) {
    asm volatile(
        "mma.sync.aligned.m16n8k16.row.col.f32.f16.f16.f32 "
        "{%0,%1,%2,%3}, {%4,%5,%6,%7}, {%8,%9}, {%0,%1,%2,%3};\n"
        : "+f"(d[0]), "+f"(d[1]), "+f"(d[2]), "+f"(d[3])
        : "r"(a[0]), "r"(a[1]), "r"(a[2]), "r"(a[3]), "r"(b0), "r"(b1));
}

__device__ __forceinline__ void ldm_x4(uint32_t* r, uint32_t addr) {
    asm volatile("ldmatrix.sync.aligned.m8n8.x4.shared.b16 {%0,%1,%2,%3}, [%4];"
                 : "=r"(r[0]), "=r"(r[1]), "=r"(r[2]), "=r"(r[3]) : "r"(addr));
}
__device__ __forceinline__ void ldm_x4_t(uint32_t* r, uint32_t addr) {
    asm volatile("ldmatrix.sync.aligned.m8n8.x4.trans.shared.b16 {%0,%1,%2,%3}, [%4];"
                 : "=r"(r[0]), "=r"(r[1]), "=r"(r[2]), "=r"(r[3]) : "r"(addr));
}

__device__ __forceinline__ uint32_t s2u(const void* p) {
    uint32_t a;
    asm("{ .reg .u64 t; cvta.to.shared.u64 t, %1; cvt.u32.u64 %0, t; }"
        : "=r"(a) : "l"(p));
    return a;
}
__device__ __forceinline__ void cpa16(uint32_t dst, const void* src) {
    asm volatile("cp.async.cg.shared.global [%0], [%1], 16;\n" :: "r"(dst), "l"(src));
}
__device__ __forceinline__ void cpa_commit() {
    asm volatile("cp.async.commit_group;\n");
}
template <int N> __device__ __forceinline__ void cpa_wait() {
    asm volatile("cp.async.wait_group %0;\n" :: "n"(N));
}

// ---------------------------------------------------------------------------
// pre-processing (canonical layouts)
// ---------------------------------------------------------------------------
__global__ void cvt_h(const float* __restrict__ in, uint32_t* __restrict__ out,
                      int nwords)
{
    int i = blockIdx.x * blockDim.x + threadIdx.x;
    if (i * 4 >= nwords) return;
    const float4* p = (const float4*)(in + (size_t)i * 8);
    float4 v0 = p[0], v1 = p[1];
    uint4 w;
    w.x = packh2(v0.x, v0.y);
    w.y = packh2(v0.z, v0.w);
    w.z = packh2(v1.x, v1.y);
    w.w = packh2(v1.z, v1.w);
    *(uint4*)(out + (size_t)i * 4) = w;
}

// in [R][C] fp32 -> out [C][R/2 words] fp16x2 (canonical).
__global__ void wtrans_h(const float* __restrict__ in, uint32_t* __restrict__ out,
                         int R, int C)
{
    __shared__ float t[32][33];
    int c0 = blockIdx.x * 32, r0 = blockIdx.y * 32;
    int tx = threadIdx.x, ty = threadIdx.y;
#pragma unroll
    for (int i = 0; i < 4; i++)
        t[ty + 8 * i][tx] = in[(size_t)(r0 + ty + 8 * i) * C + c0 + tx];
    __syncthreads();
    int Rw = R / 2;
#pragma unroll
    for (int i = 0; i < 2; i++) {
        int wp = ty + 8 * i;
        out[(size_t)(c0 + tx) * Rw + r0 / 2 + wp] =
            packh2(t[2 * wp][tx], t[2 * wp + 1][tx]);
    }
}

// ---------------------------------------------------------------------------
// fp16 GEMM, ldmatrix + XOR-swizzled smem, 3-stage single-sync pipeline.
// (unchanged from round 11)
// ---------------------------------------------------------------------------
#define GOPER  (128 * 32)            // words per operand per stage
#define GSTAGE (2 * GOPER)           // words per stage (A then B)
#define QSCALE (0.125f * 1.4426950408889634f)

template <int MODE>
__global__ __launch_bounds__(256, 2)
void gemm_h(const uint32_t* __restrict__ A, const uint32_t* __restrict__ B,
            void* __restrict__ Cv, int M, int N, int Kw)
{
    __shared__ __align__(16) uint32_t sm[3 * GSTAGE];   // 96 KB
    const uint32_t s0 = s2u(sm);

    const int tid  = threadIdx.x;
    const int lane = tid & 31;
    const int warp = tid >> 5;
    const int wm   = warp & 3;
    const int wn   = warp >> 2;
    const int bx   = blockIdx.x;
    const int by   = blockIdx.y;
    const int g    = lane >> 2;
    const int tc   = lane & 3;

    const uint32_t* Ab = A + (size_t)(by * 128) * Kw;
    const uint32_t* Bb = B + (size_t)(bx * 128) * Kw;

    float acc[2][8][4];
#pragma unroll
    for (int mt = 0; mt < 2; mt++)
#pragma unroll
        for (int nt = 0; nt < 8; nt++)
#pragma unroll
            for (int j = 0; j < 4; j++) acc[mt][nt][j] = 0.f;

    auto load_stage = [&](int s, int buf) {
        uint32_t dA = s0 + (uint32_t)(buf * GSTAGE) * 4;
        uint32_t dB = dA + (uint32_t)GOPER * 4;
#pragma unroll
        for (int j = 0; j < 4; j++) {
            int idx = tid + j * 256;
            int r = idx >> 3, ch = idx & 7;
            uint32_t sw = ((uint32_t)(r * 32) + ((ch ^ (r & 7)) << 2)) * 4;  // bytes
            cpa16(dA + sw, Ab + (size_t)r * Kw + s * 32 + ch * 4);
            cpa16(dB + sw, Bb + (size_t)r * Kw + s * 32 + ch * 4);
        }
        cpa_commit();
    };

    load_stage(0, 0);
    load_stage(1, 1);

    const int arow  = wm * 32 + (lane & 15);
    const int ahi   = lane >> 4;
    const int brow  = wn * 64 + (lane & 7) + ((lane >> 4) << 3);
    const int bhi   = (lane >> 3) & 1;
    uint32_t abase  = (uint32_t)(arow * 32) * 4;
    uint32_t bbase  = (uint32_t)(brow * 32) * 4;
    uint32_t aswz[4], bswz[4];
#pragma unroll
    for (int ks = 0; ks < 4; ks++) {
        aswz[ks] = (uint32_t)(((2 * ks + ahi) ^ (arow & 7)) << 4);
        bswz[ks] = (uint32_t)(((2 * ks + bhi) ^ (brow & 7)) << 4);
    }

    const int S = Kw / 32;
    int buf = 0;
    for (int s = 0; s < S; s++) {
        if (s + 1 < S) cpa_wait<1>(); else cpa_wait<0>();
        __syncthreads();
        if (s + 2 < S) {
            int nb = buf + 2;
            if (nb >= 3) nb -= 3;
            load_stage(s + 2, nb);
        }

        const uint32_t bA = s0 + (uint32_t)(buf * GSTAGE) * 4;
        const uint32_t bB = bA + (uint32_t)GOPER * 4;

#pragma unroll
        for (int ks = 0; ks < 4; ks++) {
            uint32_t a[2][4];
            ldm_x4(a[0], bA + abase + aswz[ks]);
            ldm_x4(a[1], bA + abase + (uint32_t)(16 * 32 * 4) + aswz[ks]);
#pragma unroll
            for (int nt2 = 0; nt2 < 4; nt2++) {
                uint32_t b[4];
                ldm_x4(b, bB + bbase + (uint32_t)(nt2 * 16 * 32 * 4) + bswz[ks]);
                mma_f16(acc[0][2 * nt2],     a[0], b[0], b[1]);
                mma_f16(acc[1][2 * nt2],     a[1], b[0], b[1]);
                mma_f16(acc[0][2 * nt2 + 1], a[0], b[2], b[3]);
                mma_f16(acc[1][2 * nt2 + 1], a[1], b[2], b[3]);
            }
        }
        buf = (buf + 1 == 3) ? 0 : buf + 1;
    }

    // epilogue
#pragma unroll
    for (int mt = 0; mt < 2; mt++)
#pragma unroll
        for (int nt = 0; nt < 8; nt++) {
            int r0 = by * 128 + wm * 32 + mt * 16 + g;
            int c0 = bx * 128 + wn * 64 + nt * 8 + 2 * tc;
            float v0 = acc[mt][nt][0], v1 = acc[mt][nt][1];
            float v2 = acc[mt][nt][2], v3 = acc[mt][nt][3];
            if (MODE == 1) {
                float sc = (c0 < DM) ? QSCALE : 1.0f;   // Q: fold 1/8 and log2e
                uint32_t* C = (uint32_t*)Cv;
                int cw = c0 >> 1;
                C[(size_t)r0 * (N / 2) + cw]       = packh2(v0 * sc, v1 * sc);
                C[(size_t)(r0 + 8) * (N / 2) + cw] = packh2(v2 * sc, v3 * sc);
            } else {
                float* C = (float*)Cv;
                *(float2*)(C + (size_t)r0 * N + c0)       = make_float2(v0, v1);
                *(float2*)(C + (size_t)(r0 + 8) * N + c0) = make_float2(v2, v3);
            }
        }
}

// ---------------------------------------------------------------------------
// Causal flash attention, fp16 mma m16n8k16. 64 q-rows, 4 warps.
// Double-buffered K/V with ONE barrier per kv-tile:
//   wait<0> (tile t landed) -> sync (visibility + buffer free) ->
//   commit load(t+1) -> compute(t).
// fp16x2 ex2 softmax + ones-MMA row sums. smem 45 KB static.
// ---------------------------------------------------------------------------
#define RW 36
#define KVBUF (64 * RW)             // words per K (or V) buffer
#define ONE2 0x3C003C00u            // (1.0h, 1.0h)
__global__ __launch_bounds__(128) void attn_fwd()
{
    __shared__ __align__(16) uint32_t smQ[64 * RW];
    __shared__ __align__(16) uint32_t smK[2 * KVBUF];
    __shared__ __align__(16) uint32_t smV[2 * KVBUF];
    const uint32_t bQ = s2u(smQ), bK = s2u(smK), bV = s2u(smV);

    const int tid  = threadIdx.x;
    const int lane = tid & 31;
    const int warp = tid >> 5;
    const int h    = blockIdx.y;
    const int qt   = (int)gridDim.x - 1 - (int)blockIdx.x;  // heavy tiles first
    const int q0   = qt * 64;
    const int g    = lane >> 2;
    const int tc   = lane & 3;

    auto load_kv = [&](int t, int buf) {
#pragma unroll
        for (int i = 0; i < 4; i++) {
            int idx = tid + i * 128;
            int r = idx >> 3, ch = idx & 7;
            const __half* base = g_qkv + (size_t)(t * 64 + r) * (3 * DM) + h * DH + ch * 8;
            uint32_t off = (uint32_t)(buf * KVBUF + r * RW + ch * 4) * 4;
            cpa16(bK + off, base + DM);
            cpa16(bV + off, base + 2 * DM);
        }
        cpa_commit();
    };

    // ---- prologue: Q + K0/V0 in one commit group ----
#pragma unroll
    for (int i = 0; i < 4; i++) {
        int idx = tid + i * 128;
        int r = idx >> 3, ch = idx & 7;
        cpa16(bQ + (uint32_t)(r * RW + ch * 4) * 4,
              g_qkv + (size_t)(q0 + r) * (3 * DM) + h * DH + ch * 8);
    }
    load_kv(0, 0);

    const uint32_t qoff = (uint32_t)((warp * 16 + (lane & 15)) * RW +
                                     ((lane >> 4) << 2)) * 4;
    const uint32_t koff = (uint32_t)(((lane & 7) + ((lane >> 4) << 3)) * RW +
                                     (((lane >> 3) & 1) << 2)) * 4;
    const uint32_t voff = (uint32_t)((lane & 15) * RW + ((lane >> 4) << 2)) * 4;

    float o[8][4];
#pragma unroll
    for (int nt = 0; nt < 8; nt++)
#pragma unroll
        for (int j = 0; j < 4; j++) o[nt][j] = 0.f;
    float mA = -INFINITY, mB = -INFINITY, lA = 0.f, lB = 0.f;

    for (int t = 0; t <= qt; t++) {
        // tile t committed in previous iteration (or prologue): only group
        // pending at this point. Retire it, then one barrier gives both
        // cross-warp visibility of tile t AND proof that compute(t-1) is done
        // on all warps (buffer (t+1)&1 free for the prefetch below).
        cpa_wait<0>();
        __syncthreads();
        if (t < qt) load_kv(t + 1, (t + 1) & 1);   // overlaps compute(t)

        const uint32_t kb = bK + (uint32_t)((t & 1) * KVBUF) * 4;
        const uint32_t vb = bV + (uint32_t)((t & 1) * KVBUF) * 4;

        // ---- S = Q @ K^T (log2-unit scores) ----
        float s[8][4];
#pragma unroll
        for (int nt = 0; nt < 8; nt++)
#pragma unroll
            for (int j = 0; j < 4; j++) s[nt][j] = 0.f;

#pragma unroll
        for (int kc = 0; kc < 4; kc++) {
            uint32_t a[4];
            ldm_x4(a, bQ + qoff + (uint32_t)(8 * kc) * 4);
#pragma unroll
            for (int ntp = 0; ntp < 4; ntp++) {
                uint32_t b[4];
                ldm_x4(b, kb + koff + (uint32_t)(ntp * 16 * RW + 8 * kc) * 4);
                mma_f16(s[2 * ntp],     a, b[0], b[1]);
                mma_f16(s[2 * ntp + 1], a, b[2], b[3]);
            }
        }

        // ---- causal mask on diagonal tile ----
        if (t == qt) {
            int qlA = warp * 16 + g;
            int qlB = qlA + 8;
#pragma unroll
            for (int nt = 0; nt < 8; nt++) {
                int k0 = nt * 8 + 2 * tc;
                if (k0     > qlA) s[nt][0] = -INFINITY;
                if (k0 + 1 > qlA) s[nt][1] = -INFINITY;
                if (k0     > qlB) s[nt][2] = -INFINITY;
                if (k0 + 1 > qlB) s[nt][3] = -INFINITY;
            }
        }

        // ---- row max (fp32, shuffles) ----
        float rA = -INFINITY, rB = -INFINITY;
#pragma unroll
        for (int nt = 0; nt < 8; nt++) {
            rA = fmaxf(rA, fmaxf(s[nt][0], s[nt][1]));
            rB = fmaxf(rB, fmaxf(s[nt][2], s[nt][3]));
        }
        rA = fmaxf(rA, __shfl_xor_sync(0xffffffffu, rA, 1));
        rA = fmaxf(rA, __shfl_xor_sync(0xffffffffu, rA, 2));
        rB = fmaxf(rB, __shfl_xor_sync(0xffffffffu, rB, 1));
        rB = fmaxf(rB, __shfl_xor_sync(0xffffffffu, rB, 2));

        float mAn = fmaxf(mA, rA), mBn = fmaxf(mB, rB);
        float fA = exp2f(mA - mAn), fB = exp2f(mB - mBn);

        // ---- exp in fp16x2; row sums via ones-MMA ----
        uint32_t pw[4][4];
        float dl[4] = {0.f, 0.f, 0.f, 0.f};
#pragma unroll
        for (int kc = 0; kc < 4; kc++) {
            pw[kc][0] = h2exp2u(packh2(s[2 * kc][0] - mAn,     s[2 * kc][1] - mAn));
            pw[kc][1] = h2exp2u(packh2(s[2 * kc][2] - mBn,     s[2 * kc][3] - mBn));
            pw[kc][2] = h2exp2u(packh2(s[2 * kc + 1][0] - mAn, s[2 * kc + 1][1] - mAn));
            pw[kc][3] = h2exp2u(packh2(s[2 * kc + 1][2] - mBn, s[2 * kc + 1][3] - mBn));
            mma_f16(dl, pw[kc], ONE2, ONE2);
        }

        lA = lA * fA + dl[0];
        lB = lB * fB + dl[2];
        mA = mAn; mB = mBn;
#pragma unroll
        for (int nt = 0; nt < 8; nt++) {
            o[nt][0] *= fA; o[nt][1] *= fA;
            o[nt][2] *= fB; o[nt][3] *= fB;
        }

        // ---- O += P @ V  (P = pw; V via ldmatrix.trans) ----
#pragma unroll
        for (int kc = 0; kc < 4; kc++) {
#pragma unroll
            for (int ntp = 0; ntp < 4; ntp++) {
                uint32_t b[4];
                ldm_x4_t(b, vb + voff + (uint32_t)(16 * kc * RW + ntp * 8) * 4);
                mma_f16(o[2 * ntp],     pw[kc], b[0], b[1]);
                mma_f16(o[2 * ntp + 1], pw[kc], b[2], b[3]);
            }
        }
    }

    // ---- epilogue: normalize, emit canonical fp16 words (proj-A input) ----
    float invA = 1.f / lA, invB = 1.f / lB;
    int rowA = q0 + warp * 16 + g;
#pragma unroll
    for (int nt = 0; nt < 8; nt++) {
        int hw = h * 32 + nt * 4 + tc;
        g_att[(size_t)rowA * KW + hw]       = packh2(o[nt][0] * invA, o[nt][1] * invA);
        g_att[(size_t)(rowA + 8) * KW + hw] = packh2(o[nt][2] * invB, o[nt][3] * invB);
    }
}

// ---------------------------------------------------------------------------
// Launch
// ---------------------------------------------------------------------------
extern "C" void kernel_launch(void* const* d_in, const int* in_sizes, int n_in,
                              void* d_out, int out_size)
{
    const float* x      = (const float*)d_in[0];
    const float* w_qkv  = (const float*)d_in[1];
    const float* w_proj = (const float*)d_in[2];
    float* out          = (float*)d_out;

    void *qkv_p, *att_p, *xw_p, *wqkvT_p, *wprojT_p;
    cudaGetSymbolAddress(&qkv_p,    g_qkv);
    cudaGetSymbolAddress(&att_p,    g_att);
    cudaGetSymbolAddress(&xw_p,     g_xw);
    cudaGetSymbolAddress(&wqkvT_p,  g_wqkvT);
    cudaGetSymbolAddress(&wprojT_p, g_wprojT);

    // 0) pre-process (canonical fp16)
    cvt_h<<<(TQ * KW / 4 + 255) / 256, 256>>>(x, (uint32_t*)xw_p, TQ * KW);
    wtrans_h<<<dim3(3 * DM / 32, DM / 32), dim3(32, 8)>>>(w_qkv, (uint32_t*)wqkvT_p,
                                                          DM, 3 * DM);
    wtrans_h<<<dim3(DM / 32, DM / 32), dim3(32, 8)>>>(w_proj, (uint32_t*)wprojT_p,
                                                      DM, DM);

    // 1) QKV projection (fp16 out; Q scaled by 0.125*log2e)
    gemm_h<1><<<dim3(3 * DM / 128, TQ / 128), 256>>>(
        (const uint32_t*)xw_p, (const uint32_t*)wqkvT_p, qkv_p, TQ, 3 * DM, KW);

    // 2) causal attention (64 q-rows/CTA, 4 warps, single-sync pipeline)
    attn_fwd<<<dim3(TQ / 64, NH), 128>>>();

    // 3) output projection (fp32 out)
    gemm_h<0><<<dim3(DM / 128, TQ / 128), 256>>>(
        (const uint32_t*)att_p, (const uint32_t*)wprojT_p, out, TQ, DM, KW);
}

// round 16
// speedup vs baseline: 1.4723x; 1.4723x over previous
#include <cuda_runtime.h>
#include <cuda_fp16.h>
#include <cstdint>
#include <cmath>

#define TQ   4096
#define DM   1024
#define NH   16
#define DH   64
#define KW   (DM / 2)          // k-dim in fp16x2 words = 512

// Scratch (__device__ globals: allocation-free rule)
__device__ __half    g_qkv[(size_t)TQ * 3 * DM];     // [t][3c] fp16, Q pre-scaled (incl log2e)
__device__ uint32_t  g_att[(size_t)TQ * KW];         // attn out fp16 words (canonical)
__device__ uint32_t  g_xw[(size_t)TQ * KW];          // x fp16 words
__device__ uint32_t  g_wqkvT[(size_t)3 * DM * KW];   // w_qkv^T fp16 words [3DM][KW]
__device__ uint32_t  g_wprojT[(size_t)DM * KW];      // w_proj^T fp16 words [DM][KW]

// ---------------------------------------------------------------------------
// helpers
// ---------------------------------------------------------------------------
__device__ __forceinline__ uint32_t packh2(float a, float b) {
    __half2 h = __floats2half2_rn(a, b);
    return *reinterpret_cast<uint32_t*>(&h);
}
__device__ __forceinline__ uint32_t h2exp2u(uint32_t x) {   // 2^x on both halves
    uint32_t r;
    asm("ex2.approx.f16x2 %0, %1;" : "=r"(r) : "r"(x));
    return r;
}

__device__ __forceinline__ void mma_f16(float* d, const uint32_t* a,
                                        uint32_t b0, uint32_t b1) {
    asm volatile(
        "mma.sync.aligned.m16n8k16.row.col.f32.f16.f16.f32 "
        "{%0,%1,%2,%3}, {%4,%5,%6,%7}, {%8,%9}, {%0,%1,%2,%3};\n"
        : "+f"(d[0]), "+f"(d[1]), "+f"(d[2]), "+f"(d[3])
        : "r"(a[0]), "r"(a[1]), "r"(a[2]), "r"(a[3]), "r"(b0), "r"(b1));
}

__device__ __forceinline__ void ldm_x4(uint32_t* r, uint32_t addr) {
    asm volatile("ldmatrix.sync.aligned.m8n8.x4.shared.b16 {%0,%1,%2,%3}, [%4];"
                 : "=r"(r[0]), "=r"(r[1]), "=r"(r[2]), "=r"(r[3]) : "r"(addr));
}
__device__ __forceinline__ void ldm_x4_t(uint32_t* r, uint32_t addr) {
    asm volatile("ldmatrix.sync.aligned.m8n8.x4.trans.shared.b16 {%0,%1,%2,%3}, [%4];"
                 : "=r"(r[0]), "=r"(r[1]), "=r"(r[2]), "=r"(r[3]) : "r"(addr));
}

__device__ __forceinline__ uint32_t s2u(const void* p) {
    uint32_t a;
    asm("{ .reg .u64 t; cvta.to.shared.u64 t, %1; cvt.u32.u64 %0, t; }"
        : "=r"(a) : "l"(p));
    return a;
}
__device__ __forceinline__ void cpa16(uint32_t dst, const void* src) {
    asm volatile("cp.async.cg.shared.global [%0], [%1], 16;\n" :: "r"(dst), "l"(src));
}
__device__ __forceinline__ void cpa_commit() {
    asm volatile("cp.async.commit_group;\n");
}
template <int N> __device__ __forceinline__ void cpa_wait() {
    asm volatile("cp.async.wait_group %0;\n" :: "n"(N));
}

// ---------------------------------------------------------------------------
// pre-processing (canonical layouts)
// ---------------------------------------------------------------------------
__global__ void cvt_h(const float* __restrict__ in, uint32_t* __restrict__ out,
                      int nwords)
{
    int i = blockIdx.x * blockDim.x + threadIdx.x;
    if (i * 4 >= nwords) return;
    const float4* p = (const float4*)(in + (size_t)i * 8);
    float4 v0 = p[0], v1 = p[1];
    uint4 w;
    w.x = packh2(v0.x, v0.y);
    w.y = packh2(v0.z, v0.w);
    w.z = packh2(v1.x, v1.y);
    w.w = packh2(v1.z, v1.w);
    *(uint4*)(out + (size_t)i * 4) = w;
}

// in [R][C] fp32 -> out [C][R/2 words] fp16x2 (canonical).
__global__ void wtrans_h(const float* __restrict__ in, uint32_t* __restrict__ out,
                         int R, int C)
{
    __shared__ float t[32][33];
    int c0 = blockIdx.x * 32, r0 = blockIdx.y * 32;
    int tx = threadIdx.x, ty = threadIdx.y;
#pragma unroll
    for (int i = 0; i < 4; i++)
        t[ty + 8 * i][tx] = in[(size_t)(r0 + ty + 8 * i) * C + c0 + tx];
    __syncthreads();
    int Rw = R / 2;
#pragma unroll
    for (int i = 0; i < 2; i++) {
        int wp = ty + 8 * i;
        out[(size_t)(c0 + tx) * Rw + r0 / 2 + wp] =
            packh2(t[2 * wp][tx], t[2 * wp + 1][tx]);
    }
}

// ---------------------------------------------------------------------------
// fp16 GEMM, ldmatrix + XOR-swizzled smem, 3-stage single-sync pipeline.
// ---------------------------------------------------------------------------
#define GOPER  (128 * 32)            // words per operand per stage
#define GSTAGE (2 * GOPER)           // words per stage (A then B)
#define QSCALE (0.125f * 1.4426950408889634f)

template <int MODE>
__global__ __launch_bounds__(256, 2)
void gemm_h(const uint32_t* __restrict__ A, const uint32_t* __restrict__ B,
            void* __restrict__ Cv, int M, int N, int Kw)
{
    __shared__ __align__(16) uint32_t sm[3 * GSTAGE];   // 96 KB
    const uint32_t s0 = s2u(sm);

    const int tid  = threadIdx.x;
    const int lane = tid & 31;
    const int warp = tid >> 5;
    const int wm   = warp & 3;
    const int wn   = warp >> 2;
    const int bx   = blockIdx.x;
    const int by   = blockIdx.y;
    const int g    = lane >> 2;
    const int tc   = lane & 3;

    const uint32_t* Ab = A + (size_t)(by * 128) * Kw;
    const uint32_t* Bb = B + (size_t)(bx * 128) * Kw;

    float acc[2][8][4];
#pragma unroll
    for (int mt = 0; mt < 2; mt++)
#pragma unroll
        for (int nt = 0; nt < 8; nt++)
#pragma unroll
            for (int j = 0; j < 4; j++) acc[mt][nt][j] = 0.f;

    auto load_stage = [&](int s, int buf) {
        uint32_t dA = s0 + (uint32_t)(buf * GSTAGE) * 4;
        uint32_t dB = dA + (uint32_t)GOPER * 4;
#pragma unroll
        for (int j = 0; j < 4; j++) {
            int idx = tid + j * 256;
            int r = idx >> 3, ch = idx & 7;
            uint32_t sw = ((uint32_t)(r * 32) + ((ch ^ (r & 7)) << 2)) * 4;  // bytes
            cpa16(dA + sw, Ab + (size_t)r * Kw + s * 32 + ch * 4);
            cpa16(dB + sw, Bb + (size_t)r * Kw + s * 32 + ch * 4);
        }
        cpa_commit();
    };

    load_stage(0, 0);
    load_stage(1, 1);

    const int arow  = wm * 32 + (lane & 15);
    const int ahi   = lane >> 4;
    const int brow  = wn * 64 + (lane & 7) + ((lane >> 4) << 3);
    const int bhi   = (lane >> 3) & 1;
    uint32_t abase  = (uint32_t)(arow * 32) * 4;
    uint32_t bbase  = (uint32_t)(brow * 32) * 4;
    uint32_t aswz[4], bswz[4];
#pragma unroll
    for (int ks = 0; ks < 4; ks++) {
        aswz[ks] = (uint32_t)(((2 * ks + ahi) ^ (arow & 7)) << 4);
        bswz[ks] = (uint32_t)(((2 * ks + bhi) ^ (brow & 7)) << 4);
    }

    const int S = Kw / 32;
    int buf = 0;
    for (int s = 0; s < S; s++) {
        if (s + 1 < S) cpa_wait<1>(); else cpa_wait<0>();
        __syncthreads();
        if (s + 2 < S) {
            int nb = buf + 2;
            if (nb >= 3) nb -= 3;
            load_stage(s + 2, nb);
        }

        const uint32_t bA = s0 + (uint32_t)(buf * GSTAGE) * 4;
        const uint32_t bB = bA + (uint32_t)GOPER * 4;

#pragma unroll
        for (int ks = 0; ks < 4; ks++) {
            uint32_t a[2][4];
            ldm_x4(a[0], bA + abase + aswz[ks]);
            ldm_x4(a[1], bA + abase + (uint32_t)(16 * 32 * 4) + aswz[ks]);
#pragma unroll
            for (int nt2 = 0; nt2 < 4; nt2++) {
                uint32_t b[4];
                ldm_x4(b, bB + bbase + (uint32_t)(nt2 * 16 * 32 * 4) + bswz[ks]);
                mma_f16(acc[0][2 * nt2],     a[0], b[0], b[1]);
                mma_f16(acc[1][2 * nt2],     a[1], b[0], b[1]);
                mma_f16(acc[0][2 * nt2 + 1], a[0], b[2], b[3]);
                mma_f16(acc[1][2 * nt2 + 1], a[1], b[2], b[3]);
            }
        }
        buf = (buf + 1 == 3) ? 0 : buf + 1;
    }

    // epilogue
#pragma unroll
    for (int mt = 0; mt < 2; mt++)
#pragma unroll
        for (int nt = 0; nt < 8; nt++) {
            int r0 = by * 128 + wm * 32 + mt * 16 + g;
            int c0 = bx * 128 + wn * 64 + nt * 8 + 2 * tc;
            float v0 = acc[mt][nt][0], v1 = acc[mt][nt][1];
            float v2 = acc[mt][nt][2], v3 = acc[mt][nt][3];
            if (MODE == 1) {
                float sc = (c0 < DM) ? QSCALE : 1.0f;   // Q: fold 1/8 and log2e
                uint32_t* C = (uint32_t*)Cv;
                int cw = c0 >> 1;
                C[(size_t)r0 * (N / 2) + cw]       = packh2(v0 * sc, v1 * sc);
                C[(size_t)(r0 + 8) * (N / 2) + cw] = packh2(v2 * sc, v3 * sc);
            } else {
                float* C = (float*)Cv;
                *(float2*)(C + (size_t)r0 * N + c0)       = make_float2(v0, v1);
                *(float2*)(C + (size_t)(r0 + 8) * N + c0) = make_float2(v2, v3);
            }
        }
}

// ---------------------------------------------------------------------------
// Causal flash attention, fp16 mma m16n8k16. 64 q-rows, 4 warps.
// Double-buffered K/V (load t+1 overlaps compute t; round-13 proven
// schedule). fp16x2 ex2 softmax + ones-MMA row sums. smem 45 KB static.
// ---------------------------------------------------------------------------
#define RW 36
#define KVBUF (64 * RW)             // words per K (or V) buffer
#define ONE2 0x3C003C00u            // (1.0h, 1.0h)
__global__ __launch_bounds__(128) void attn_fwd()
{
    __shared__ __align__(16) uint32_t smQ[64 * RW];
    __shared__ __align__(16) uint32_t smK[2 * KVBUF];
    __shared__ __align__(16) uint32_t smV[2 * KVBUF];
    const uint32_t bQ = s2u(smQ), bK = s2u(smK), bV = s2u(smV);

    const int tid  = threadIdx.x;
    const int lane = tid & 31;
    const int warp = tid >> 5;
    const int h    = blockIdx.y;
    const int qt   = (int)gridDim.x - 1 - (int)blockIdx.x;  // heavy tiles first
    const int q0   = qt * 64;
    const int g    = lane >> 2;
    const int tc   = lane & 3;

    auto load_kv = [&](int t, int buf) {
#pragma unroll
        for (int i = 0; i < 4; i++) {
            int idx = tid + i * 128;
            int r = idx >> 3, ch = idx & 7;
            const __half* base = g_qkv + (size_t)(t * 64 + r) * (3 * DM) + h * DH + ch * 8;
            uint32_t off = (uint32_t)(buf * KVBUF + r * RW + ch * 4) * 4;
            cpa16(bK + off, base + DM);
            cpa16(bV + off, base + 2 * DM);
        }
    };

    // ---- prologue: Q + K0/V0 in one commit group ----
#pragma unroll
    for (int i = 0; i < 4; i++) {
        int idx = tid + i * 128;
        int r = idx >> 3, ch = idx & 7;
        cpa16(bQ + (uint32_t)(r * RW + ch * 4) * 4,
              g_qkv + (size_t)(q0 + r) * (3 * DM) + h * DH + ch * 8);
    }
    load_kv(0, 0);
    cpa_commit();

    const uint32_t qoff = (uint32_t)((warp * 16 + (lane & 15)) * RW +
                                     ((lane >> 4) << 2)) * 4;
    const uint32_t koff = (uint32_t)(((lane & 7) + ((lane >> 4) << 3)) * RW +
                                     (((lane >> 3) & 1) << 2)) * 4;
    const uint32_t voff = (uint32_t)((lane & 15) * RW + ((lane >> 4) << 2)) * 4;

    float o[8][4];
#pragma unroll
    for (int nt = 0; nt < 8; nt++)
#pragma unroll
        for (int j = 0; j < 4; j++) o[nt][j] = 0.f;
    float mA = -INFINITY, mB = -INFINITY, lA = 0.f, lB = 0.f;

    for (int t = 0; t <= qt; t++) {
        __syncthreads();               // all warps done with buffer (t+1)&1
        if (t < qt) {                  // prefetch t+1 (overlaps compute t)
            load_kv(t + 1, (t + 1) & 1);
            cpa_commit();
            cpa_wait<1>();             // tile t landed, t+1 in flight
        } else {
            cpa_wait<0>();
        }
        __syncthreads();               // tile t visible to all warps

        const uint32_t kb = bK + (uint32_t)((t & 1) * KVBUF) * 4;
        const uint32_t vb = bV + (uint32_t)((t & 1) * KVBUF) * 4;

        // ---- S = Q @ K^T (log2-unit scores) ----
        float s[8][4];
#pragma unroll
        for (int nt = 0; nt < 8; nt++)
#pragma unroll
            for (int j = 0; j < 4; j++) s[nt][j] = 0.f;

#pragma unroll
        for (int kc = 0; kc < 4; kc++) {
            uint32_t a[4];
            ldm_x4(a, bQ + qoff + (uint32_t)(8 * kc) * 4);
#pragma unroll
            for (int ntp = 0; ntp < 4; ntp++) {
                uint32_t b[4];
                ldm_x4(b, kb + koff + (uint32_t)(ntp * 16 * RW + 8 * kc) * 4);
                mma_f16(s[2 * ntp],     a, b[0], b[1]);
                mma_f16(s[2 * ntp + 1], a, b[2], b[3]);
            }
        }

        // ---- causal mask on diagonal tile ----
        if (t == qt) {
            int qlA = warp * 16 + g;
            int qlB = qlA + 8;
#pragma unroll
            for (int nt = 0; nt < 8; nt++) {
                int k0 = nt * 8 + 2 * tc;
                if (k0     > qlA) s[nt][0] = -INFINITY;
                if (k0 + 1 > qlA) s[nt][1] = -INFINITY;
                if (k0     > qlB) s[nt][2] = -INFINITY;
                if (k0 + 1 > qlB) s[nt][3] = -INFINITY;
            }
        }

        // ---- row max (fp32, shuffles) ----
        float rA = -INFINITY, rB = -INFINITY;
#pragma unroll
        for (int nt = 0; nt < 8; nt++) {
            rA = fmaxf(rA, fmaxf(s[nt][0], s[nt][1]));
            rB = fmaxf(rB, fmaxf(s[nt][2], s[nt][3]));
        }
        rA = fmaxf(rA, __shfl_xor_sync(0xffffffffu, rA, 1));
        rA = fmaxf(rA, __shfl_xor_sync(0xffffffffu, rA, 2));
        rB = fmaxf(rB, __shfl_xor_sync(0xffffffffu, rB, 1));
        rB = fmaxf(rB, __shfl_xor_sync(0xffffffffu, rB, 2));

        float mAn = fmaxf(mA, rA), mBn = fmaxf(mB, rB);
        float fA = exp2f(mA - mAn), fB = exp2f(mB - mBn);

        // ---- exp in fp16x2; row sums via ones-MMA ----
        uint32_t pw[4][4];
        float dl[4] = {0.f, 0.f, 0.f, 0.f};
#pragma unroll
        for (int kc = 0; kc < 4; kc++) {
            pw[kc][0] = h2exp2u(packh2(s[2 * kc][0] - mAn,     s[2 * kc][1] - mAn));
            pw[kc][1] = h2exp2u(packh2(s[2 * kc][2] - mBn,     s[2 * kc][3] - mBn));
            pw[kc][2] = h2exp2u(packh2(s[2 * kc + 1][0] - mAn, s[2 * kc + 1][1] - mAn));
            pw[kc][3] = h2exp2u(packh2(s[2 * kc + 1][2] - mBn, s[2 * kc + 1][3] - mBn));
            mma_f16(dl, pw[kc], ONE2, ONE2);
        }

        lA = lA * fA + dl[0];
        lB = lB * fB + dl[2];
        mA = mAn; mB = mBn;
#pragma unroll
        for (int nt = 0; nt < 8; nt++) {
            o[nt][0] *= fA; o[nt][1] *= fA;
            o[nt][2] *= fB; o[nt][3] *= fB;
        }

        // ---- O += P @ V  (P = pw; V via ldmatrix.trans) ----
#pragma unroll
        for (int kc = 0; kc < 4; kc++) {
#pragma unroll
            for (int ntp = 0; ntp < 4; ntp++) {
                uint32_t b[4];
                ldm_x4_t(b, vb + voff + (uint32_t)(16 * kc * RW + ntp * 8) * 4);
                mma_f16(o[2 * ntp],     pw[kc], b[0], b[1]);
                mma_f16(o[2 * ntp + 1], pw[kc], b[2], b[3]);
            }
        }
    }

    // ---- epilogue: normalize, emit canonical fp16 words (proj-A input) ----
    float invA = 1.f / lA, invB = 1.f / lB;
    int rowA = q0 + warp * 16 + g;
#pragma unroll
    for (int nt = 0; nt < 8; nt++) {
        int hw = h * 32 + nt * 4 + tc;
        g_att[(size_t)rowA * KW + hw]       = packh2(o[nt][0] * invA, o[nt][1] * invA);
        g_att[(size_t)(rowA + 8) * KW + hw] = packh2(o[nt][2] * invB, o[nt][3] * invB);
    }
}

// ---------------------------------------------------------------------------
// Launch
// ---------------------------------------------------------------------------
extern "C" void kernel_launch(void* const* d_in, const int* in_sizes, int n_in,
                              void* d_out, int out_size)
{
    const float* x      = (const float*)d_in[0];
    const float* w_qkv  = (const float*)d_in[1];
    const float* w_proj = (const float*)d_in[2];
    float* out          = (float*)d_out;

    void *qkv_p, *att_p, *xw_p, *wqkvT_p, *wprojT_p;
    cudaGetSymbolAddress(&qkv_p,    g_qkv);
    cudaGetSymbolAddress(&att_p,    g_att);
    cudaGetSymbolAddress(&xw_p,     g_xw);
    cudaGetSymbolAddress(&wqkvT_p,  g_wqkvT);
    cudaGetSymbolAddress(&wprojT_p, g_wprojT);

    // 0) pre-process (canonical fp16)
    cvt_h<<<(TQ * KW / 4 + 255) / 256, 256>>>(x, (uint32_t*)xw_p, TQ * KW);
    wtrans_h<<<dim3(3 * DM / 32, DM / 32), dim3(32, 8)>>>(w_qkv, (uint32_t*)wqkvT_p,
                                                          DM, 3 * DM);
    wtrans_h<<<dim3(DM / 32, DM / 32), dim3(32, 8)>>>(w_proj, (uint32_t*)wprojT_p,
                                                      DM, DM);

    // 1) QKV projection (fp16 out; Q scaled by 0.125*log2e)
    gemm_h<1><<<dim3(3 * DM / 128, TQ / 128), 256>>>(
        (const uint32_t*)xw_p, (const uint32_t*)wqkvT_p, qkv_p, TQ, 3 * DM, KW);

    // 2) causal attention (64 q-rows/CTA, 4 warps, double-buffered K/V)
    attn_fwd<<<dim3(TQ / 64, NH), 128>>>();

    // 3) output projection (fp32 out)
    gemm_h<0><<<dim3(DM / 128, TQ / 128), 256>>>(
        (const uint32_t*)att_p, (const uint32_t*)wprojT_p, out, TQ, DM, KW);
}

// round 17
// speedup vs baseline: 1.4861x; 1.0094x over previous
#include <cuda_runtime.h>
#include <cuda_fp16.h>
#include <cstdint>
#include <cmath>

#define TQ   4096
#define DM   1024
#define NH   16
#define DH   64
#define KW   (DM / 2)          // k-dim in fp16x2 words = 512

// Scratch (__device__ globals: allocation-free rule)
__device__ __half    g_qkv[(size_t)TQ * 3 * DM];     // [t][3c] fp16, Q pre-scaled (incl log2e)
__device__ uint32_t  g_att[(size_t)TQ * KW];         // attn out fp16 words (canonical)
__device__ uint32_t  g_xw[(size_t)TQ * KW];          // x fp16 words
__device__ uint32_t  g_wqkvT[(size_t)3 * DM * KW];   // w_qkv^T fp16 words [3DM][KW]
__device__ uint32_t  g_wprojT[(size_t)DM * KW];      // w_proj^T fp16 words [DM][KW]

// ---------------------------------------------------------------------------
// helpers
// ---------------------------------------------------------------------------
__device__ __forceinline__ uint32_t packh2(float a, float b) {
    __half2 h = __floats2half2_rn(a, b);
    return *reinterpret_cast<uint32_t*>(&h);
}
__device__ __forceinline__ uint32_t h2exp2u(uint32_t x) {   // 2^x on both halves
    uint32_t r;
    asm("ex2.approx.f16x2 %0, %1;" : "=r"(r) : "r"(x));
    return r;
}

__device__ __forceinline__ void mma_f16(float* d, const uint32_t* a,
                                        uint32_t b0, uint32_t b1) {
    asm volatile(
        "mma.sync.aligned.m16n8k16.row.col.f32.f16.f16.f32 "
        "{%0,%1,%2,%3}, {%4,%5,%6,%7}, {%8,%9}, {%0,%1,%2,%3};\n"
        : "+f"(d[0]), "+f"(d[1]), "+f"(d[2]), "+f"(d[3])
        : "r"(a[0]), "r"(a[1]), "r"(a[2]), "r"(a[3]), "r"(b0), "r"(b1));
}

__device__ __forceinline__ void ldm_x4(uint32_t* r, uint32_t addr) {
    asm volatile("ldmatrix.sync.aligned.m8n8.x4.shared.b16 {%0,%1,%2,%3}, [%4];"
                 : "=r"(r[0]), "=r"(r[1]), "=r"(r[2]), "=r"(r[3]) : "r"(addr));
}
__device__ __forceinline__ void ldm_x4_t(uint32_t* r, uint32_t addr) {
    asm volatile("ldmatrix.sync.aligned.m8n8.x4.trans.shared.b16 {%0,%1,%2,%3}, [%4];"
                 : "=r"(r[0]), "=r"(r[1]), "=r"(r[2]), "=r"(r[3]) : "r"(addr));
}

__device__ __forceinline__ uint32_t s2u(const void* p) {
    uint32_t a;
    asm("{ .reg .u64 t; cvta.to.shared.u64 t, %1; cvt.u32.u64 %0, t; }"
        : "=r"(a) : "l"(p));
    return a;
}
__device__ __forceinline__ void cpa16(uint32_t dst, const void* src) {
    asm volatile("cp.async.cg.shared.global [%0], [%1], 16;\n" :: "r"(dst), "l"(src));
}
__device__ __forceinline__ void cpa_commit() {
    asm volatile("cp.async.commit_group;\n");
}
template <int N> __device__ __forceinline__ void cpa_wait() {
    asm volatile("cp.async.wait_group %0;\n" :: "n"(N));
}

// ---------------------------------------------------------------------------
// pre-processing (canonical layouts)
// ---------------------------------------------------------------------------
__global__ void cvt_h(const float* __restrict__ in, uint32_t* __restrict__ out,
                      int nwords)
{
    int i = blockIdx.x * blockDim.x + threadIdx.x;
    if (i * 4 >= nwords) return;
    const float4* p = (const float4*)(in + (size_t)i * 8);
    float4 v0 = p[0], v1 = p[1];
    uint4 w;
    w.x = packh2(v0.x, v0.y);
    w.y = packh2(v0.z, v0.w);
    w.z = packh2(v1.x, v1.y);
    w.w = packh2(v1.z, v1.w);
    *(uint4*)(out + (size_t)i * 4) = w;
}

// in [R][C] fp32 -> out [C][R/2 words] fp16x2 (canonical).
__global__ void wtrans_h(const float* __restrict__ in, uint32_t* __restrict__ out,
                         int R, int C)
{
    __shared__ float t[32][33];
    int c0 = blockIdx.x * 32, r0 = blockIdx.y * 32;
    int tx = threadIdx.x, ty = threadIdx.y;
#pragma unroll
    for (int i = 0; i < 4; i++)
        t[ty + 8 * i][tx] = in[(size_t)(r0 + ty + 8 * i) * C + c0 + tx];
    __syncthreads();
    int Rw = R / 2;
#pragma unroll
    for (int i = 0; i < 2; i++) {
        int wp = ty + 8 * i;
        out[(size_t)(c0 + tx) * Rw + r0 / 2 + wp] =
            packh2(t[2 * wp][tx], t[2 * wp + 1][tx]);
    }
}

// ---------------------------------------------------------------------------
// fp16 GEMM, ldmatrix + XOR-swizzled smem, 3-stage single-sync pipeline.
// (byte-identical to round 16 — serves as the clock canary)
// ---------------------------------------------------------------------------
#define GOPER  (128 * 32)            // words per operand per stage
#define GSTAGE (2 * GOPER)           // words per stage (A then B)
#define QSCALE (0.125f * 1.4426950408889634f)

template <int MODE>
__global__ __launch_bounds__(256, 2)
void gemm_h(const uint32_t* __restrict__ A, const uint32_t* __restrict__ B,
            void* __restrict__ Cv, int M, int N, int Kw)
{
    __shared__ __align__(16) uint32_t sm[3 * GSTAGE];   // 96 KB
    const uint32_t s0 = s2u(sm);

    const int tid  = threadIdx.x;
    const int lane = tid & 31;
    const int warp = tid >> 5;
    const int wm   = warp & 3;
    const int wn   = warp >> 2;
    const int bx   = blockIdx.x;
    const int by   = blockIdx.y;
    const int g    = lane >> 2;
    const int tc   = lane & 3;

    const uint32_t* Ab = A + (size_t)(by * 128) * Kw;
    const uint32_t* Bb = B + (size_t)(bx * 128) * Kw;

    float acc[2][8][4];
#pragma unroll
    for (int mt = 0; mt < 2; mt++)
#pragma unroll
        for (int nt = 0; nt < 8; nt++)
#pragma unroll
            for (int j = 0; j < 4; j++) acc[mt][nt][j] = 0.f;

    auto load_stage = [&](int s, int buf) {
        uint32_t dA = s0 + (uint32_t)(buf * GSTAGE) * 4;
        uint32_t dB = dA + (uint32_t)GOPER * 4;
#pragma unroll
        for (int j = 0; j < 4; j++) {
            int idx = tid + j * 256;
            int r = idx >> 3, ch = idx & 7;
            uint32_t sw = ((uint32_t)(r * 32) + ((ch ^ (r & 7)) << 2)) * 4;  // bytes
            cpa16(dA + sw, Ab + (size_t)r * Kw + s * 32 + ch * 4);
            cpa16(dB + sw, Bb + (size_t)r * Kw + s * 32 + ch * 4);
        }
        cpa_commit();
    };

    load_stage(0, 0);
    load_stage(1, 1);

    const int arow  = wm * 32 + (lane & 15);
    const int ahi   = lane >> 4;
    const int brow  = wn * 64 + (lane & 7) + ((lane >> 4) << 3);
    const int bhi   = (lane >> 3) & 1;
    uint32_t abase  = (uint32_t)(arow * 32) * 4;
    uint32_t bbase  = (uint32_t)(brow * 32) * 4;
    uint32_t aswz[4], bswz[4];
#pragma unroll
    for (int ks = 0; ks < 4; ks++) {
        aswz[ks] = (uint32_t)(((2 * ks + ahi) ^ (arow & 7)) << 4);
        bswz[ks] = (uint32_t)(((2 * ks + bhi) ^ (brow & 7)) << 4);
    }

    const int S = Kw / 32;
    int buf = 0;
    for (int s = 0; s < S; s++) {
        if (s + 1 < S) cpa_wait<1>(); else cpa_wait<0>();
        __syncthreads();
        if (s + 2 < S) {
            int nb = buf + 2;
            if (nb >= 3) nb -= 3;
            load_stage(s + 2, nb);
        }

        const uint32_t bA = s0 + (uint32_t)(buf * GSTAGE) * 4;
        const uint32_t bB = bA + (uint32_t)GOPER * 4;

#pragma unroll
        for (int ks = 0; ks < 4; ks++) {
            uint32_t a[2][4];
            ldm_x4(a[0], bA + abase + aswz[ks]);
            ldm_x4(a[1], bA + abase + (uint32_t)(16 * 32 * 4) + aswz[ks]);
#pragma unroll
            for (int nt2 = 0; nt2 < 4; nt2++) {
                uint32_t b[4];
                ldm_x4(b, bB + bbase + (uint32_t)(nt2 * 16 * 32 * 4) + bswz[ks]);
                mma_f16(acc[0][2 * nt2],     a[0], b[0], b[1]);
                mma_f16(acc[1][2 * nt2],     a[1], b[0], b[1]);
                mma_f16(acc[0][2 * nt2 + 1], a[0], b[2], b[3]);
                mma_f16(acc[1][2 * nt2 + 1], a[1], b[2], b[3]);
            }
        }
        buf = (buf + 1 == 3) ? 0 : buf + 1;
    }

    // epilogue
#pragma unroll
    for (int mt = 0; mt < 2; mt++)
#pragma unroll
        for (int nt = 0; nt < 8; nt++) {
            int r0 = by * 128 + wm * 32 + mt * 16 + g;
            int c0 = bx * 128 + wn * 64 + nt * 8 + 2 * tc;
            float v0 = acc[mt][nt][0], v1 = acc[mt][nt][1];
            float v2 = acc[mt][nt][2], v3 = acc[mt][nt][3];
            if (MODE == 1) {
                float sc = (c0 < DM) ? QSCALE : 1.0f;   // Q: fold 1/8 and log2e
                uint32_t* C = (uint32_t*)Cv;
                int cw = c0 >> 1;
                C[(size_t)r0 * (N / 2) + cw]       = packh2(v0 * sc, v1 * sc);
                C[(size_t)(r0 + 8) * (N / 2) + cw] = packh2(v2 * sc, v3 * sc);
            } else {
                float* C = (float*)Cv;
                *(float2*)(C + (size_t)r0 * N + c0)       = make_float2(v0, v1);
                *(float2*)(C + (size_t)(r0 + 8) * N + c0) = make_float2(v2, v3);
            }
        }
}

// ---------------------------------------------------------------------------
// Causal flash attention, fp16 mma m16n8k16. 64 q-rows, 4 warps.
// Single-barrier double-buffered K/V pipeline:
//   iter t: [t>0: wait<0>, sync] -> commit load(t+1) -> compute(t)
// Q fragments hoisted to registers (loaded once). fp16x2 ex2 softmax +
// ones-MMA row sums. smem 45 KB static.
// ---------------------------------------------------------------------------
#define RW 36
#define KVBUF (64 * RW)             // words per K (or V) buffer
#define ONE2 0x3C003C00u            // (1.0h, 1.0h)
__global__ __launch_bounds__(128) void attn_fwd()
{
    __shared__ __align__(16) uint32_t smQ[64 * RW];
    __shared__ __align__(16) uint32_t smK[2 * KVBUF];
    __shared__ __align__(16) uint32_t smV[2 * KVBUF];
    const uint32_t bQ = s2u(smQ), bK = s2u(smK), bV = s2u(smV);

    const int tid  = threadIdx.x;
    const int lane = tid & 31;
    const int warp = tid >> 5;
    const int h    = blockIdx.y;
    const int qt   = (int)gridDim.x - 1 - (int)blockIdx.x;  // heavy tiles first
    const int q0   = qt * 64;
    const int g    = lane >> 2;
    const int tc   = lane & 3;

    auto load_kv = [&](int t, int buf) {
#pragma unroll
        for (int i = 0; i < 4; i++) {
            int idx = tid + i * 128;
            int r = idx >> 3, ch = idx & 7;
            const __half* base = g_qkv + (size_t)(t * 64 + r) * (3 * DM) + h * DH + ch * 8;
            uint32_t off = (uint32_t)(buf * KVBUF + r * RW + ch * 4) * 4;
            cpa16(bK + off, base + DM);
            cpa16(bV + off, base + 2 * DM);
        }
        cpa_commit();
    };

    // ---- prologue: Q + K0/V0 in one commit group ----
#pragma unroll
    for (int i = 0; i < 4; i++) {
        int idx = tid + i * 128;
        int r = idx >> 3, ch = idx & 7;
        cpa16(bQ + (uint32_t)(r * RW + ch * 4) * 4,
              g_qkv + (size_t)(q0 + r) * (3 * DM) + h * DH + ch * 8);
    }
    load_kv(0, 0);

    const uint32_t qoff = (uint32_t)((warp * 16 + (lane & 15)) * RW +
                                     ((lane >> 4) << 2)) * 4;
    const uint32_t koff = (uint32_t)(((lane & 7) + ((lane >> 4) << 3)) * RW +
                                     (((lane >> 3) & 1) << 2)) * 4;
    const uint32_t voff = (uint32_t)((lane & 15) * RW + ((lane >> 4) << 2)) * 4;

    // ---- wait for Q + tile 0, hoist Q fragments into registers ----
    cpa_wait<0>();
    __syncthreads();
    uint32_t qr[4][4];
#pragma unroll
    for (int kc = 0; kc < 4; kc++)
        ldm_x4(qr[kc], bQ + qoff + (uint32_t)(8 * kc) * 4);

    float o[8][4];
#pragma unroll
    for (int nt = 0; nt < 8; nt++)
#pragma unroll
        for (int j = 0; j < 4; j++) o[nt][j] = 0.f;
    float mA = -INFINITY, mB = -INFINITY, lA = 0.f, lB = 0.f;

    for (int t = 0; t <= qt; t++) {
        if (t > 0) {
            cpa_wait<0>();     // tile t landed (committed last iteration)
            __syncthreads();   // visibility + all warps done compute(t-1)
        }
        if (t < qt) load_kv(t + 1, (t + 1) & 1);   // overlaps compute(t)

        const uint32_t kb = bK + (uint32_t)((t & 1) * KVBUF) * 4;
        const uint32_t vb = bV + (uint32_t)((t & 1) * KVBUF) * 4;

        // ---- S = Q @ K^T (log2-unit scores) ----
        float s[8][4];
#pragma unroll
        for (int nt = 0; nt < 8; nt++)
#pragma unroll
            for (int j = 0; j < 4; j++) s[nt][j] = 0.f;

#pragma unroll
        for (int kc = 0; kc < 4; kc++) {
#pragma unroll
            for (int ntp = 0; ntp < 4; ntp++) {
                uint32_t b[4];
                ldm_x4(b, kb + koff + (uint32_t)(ntp * 16 * RW + 8 * kc) * 4);
                mma_f16(s[2 * ntp],     qr[kc], b[0], b[1]);
                mma_f16(s[2 * ntp + 1], qr[kc], b[2], b[3]);
            }
        }

        // ---- causal mask on diagonal tile ----
        if (t == qt) {
            int qlA = warp * 16 + g;
            int qlB = qlA + 8;
#pragma unroll
            for (int nt = 0; nt < 8; nt++) {
                int k0 = nt * 8 + 2 * tc;
                if (k0     > qlA) s[nt][0] = -INFINITY;
                if (k0 + 1 > qlA) s[nt][1] = -INFINITY;
                if (k0     > qlB) s[nt][2] = -INFINITY;
                if (k0 + 1 > qlB) s[nt][3] = -INFINITY;
            }
        }

        // ---- row max (fp32, shuffles) ----
        float rA = -INFINITY, rB = -INFINITY;
#pragma unroll
        for (int nt = 0; nt < 8; nt++) {
            rA = fmaxf(rA, fmaxf(s[nt][0], s[nt][1]));
            rB = fmaxf(rB, fmaxf(s[nt][2], s[nt][3]));
        }
        rA = fmaxf(rA, __shfl_xor_sync(0xffffffffu, rA, 1));
        rA = fmaxf(rA, __shfl_xor_sync(0xffffffffu, rA, 2));
        rB = fmaxf(rB, __shfl_xor_sync(0xffffffffu, rB, 1));
        rB = fmaxf(rB, __shfl_xor_sync(0xffffffffu, rB, 2));

        float mAn = fmaxf(mA, rA), mBn = fmaxf(mB, rB);
        float fA = exp2f(mA - mAn), fB = exp2f(mB - mBn);

        // ---- exp in fp16x2; row sums via ones-MMA ----
        uint32_t pw[4][4];
        float dl[4] = {0.f, 0.f, 0.f, 0.f};
#pragma unroll
        for (int kc = 0; kc < 4; kc++) {
            pw[kc][0] = h2exp2u(packh2(s[2 * kc][0] - mAn,     s[2 * kc][1] - mAn));
            pw[kc][1] = h2exp2u(packh2(s[2 * kc][2] - mBn,     s[2 * kc][3] - mBn));
            pw[kc][2] = h2exp2u(packh2(s[2 * kc + 1][0] - mAn, s[2 * kc + 1][1] - mAn));
            pw[kc][3] = h2exp2u(packh2(s[2 * kc + 1][2] - mBn, s[2 * kc + 1][3] - mBn));
            mma_f16(dl, pw[kc], ONE2, ONE2);
        }

        lA = lA * fA + dl[0];
        lB = lB * fB + dl[2];
        mA = mAn; mB = mBn;
#pragma unroll
        for (int nt = 0; nt < 8; nt++) {
            o[nt][0] *= fA; o[nt][1] *= fA;
            o[nt][2] *= fB; o[nt][3] *= fB;
        }

        // ---- O += P @ V  (P = pw; V via ldmatrix.trans) ----
#pragma unroll
        for (int kc = 0; kc < 4; kc++) {
#pragma unroll
            for (int ntp = 0; ntp < 4; ntp++) {
                uint32_t b[4];
                ldm_x4_t(b, vb + voff + (uint32_t)(16 * kc * RW + ntp * 8) * 4);
                mma_f16(o[2 * ntp],     pw[kc], b[0], b[1]);
                mma_f16(o[2 * ntp + 1], pw[kc], b[2], b[3]);
            }
        }
    }

    // ---- epilogue: normalize, emit canonical fp16 words (proj-A input) ----
    float invA = 1.f / lA, invB = 1.f / lB;
    int rowA = q0 + warp * 16 + g;
#pragma unroll
    for (int nt = 0; nt < 8; nt++) {
        int hw = h * 32 + nt * 4 + tc;
        g_att[(size_t)rowA * KW + hw]       = packh2(o[nt][0] * invA, o[nt][1] * invA);
        g_att[(size_t)(rowA + 8) * KW + hw] = packh2(o[nt][2] * invB, o[nt][3] * invB);
    }
}

// ---------------------------------------------------------------------------
// Launch
// ---------------------------------------------------------------------------
extern "C" void kernel_launch(void* const* d_in, const int* in_sizes, int n_in,
                              void* d_out, int out_size)
{
    const float* x      = (const float*)d_in[0];
    const float* w_qkv  = (const float*)d_in[1];
    const float* w_proj = (const float*)d_in[2];
    float* out          = (float*)d_out;

    void *qkv_p, *att_p, *xw_p, *wqkvT_p, *wprojT_p;
    cudaGetSymbolAddress(&qkv_p,    g_qkv);
    cudaGetSymbolAddress(&att_p,    g_att);
    cudaGetSymbolAddress(&xw_p,     g_xw);
    cudaGetSymbolAddress(&wqkvT_p,  g_wqkvT);
    cudaGetSymbolAddress(&wprojT_p, g_wprojT);

    // 0) pre-process (canonical fp16)
    cvt_h<<<(TQ * KW / 4 + 255) / 256, 256>>>(x, (uint32_t*)xw_p, TQ * KW);
    wtrans_h<<<dim3(3 * DM / 32, DM / 32), dim3(32, 8)>>>(w_qkv, (uint32_t*)wqkvT_p,
                                                          DM, 3 * DM);
    wtrans_h<<<dim3(DM / 32, DM / 32), dim3(32, 8)>>>(w_proj, (uint32_t*)wprojT_p,
                                                      DM, DM);

    // 1) QKV projection (fp16 out; Q scaled by 0.125*log2e)
    gemm_h<1><<<dim3(3 * DM / 128, TQ / 128), 256>>>(
        (const uint32_t*)xw_p, (const uint32_t*)wqkvT_p, qkv_p, TQ, 3 * DM, KW);

    // 2) causal attention (64 q-rows/CTA, 4 warps, single-barrier pipeline)
    attn_fwd<<<dim3(TQ / 64, NH), 128>>>();

    // 3) output projection (fp32 out)
    gemm_h<0><<<dim3(DM / 128, TQ / 128), 256>>>(
        (const uint32_t*)att_p, (const uint32_t*)wprojT_p, out, TQ, DM, KW);
}